// round 4
// baseline (speedup 1.0000x reference)
#include <cuda_runtime.h>

#define NN 100000
#define NE 1200000
#define D  64

// Scratch (device globals — no allocation allowed)
__device__ float g_dis[NN];        // degree, then rsqrt(degree)
__device__ float g_h[NN * D];      // h = x @ W^T

// ---------------------------------------------------------------------------
__global__ void k_init_deg() {
    int i = blockIdx.x * blockDim.x + threadIdx.x;
    if (i < NN) g_dis[i] = 1.0f;   // self-loop weight
}

__global__ void k_deg(const int* __restrict__ dst, const float* __restrict__ ew) {
    int e = blockIdx.x * blockDim.x + threadIdx.x;
    if (e < NE) atomicAdd(&g_dis[dst[e]], ew[e]);
}

__global__ void k_rsqrt() {
    int i = blockIdx.x * blockDim.x + threadIdx.x;
    if (i < NN) g_dis[i] = rsqrtf(g_dis[i]);
}

// ---------------------------------------------------------------------------
// GEMM h = x @ W^T fused with self-loop term (out = dis^2 * h).
// 256 threads, 96 rows/block. Thread (cg,rg): cols [8cg,8cg+8), rows rg+{0,32,64}.
// k-loop chunked by 4: X via LDS.128 (stride-68 rows -> conflict-free).
#define GROWS 96
#define XSTRIDE 68
__global__ __launch_bounds__(256) void k_gemm(const float* __restrict__ x,
                                              const float* __restrict__ W,
                                              float* __restrict__ out) {
    __shared__ float Wt[D * D];            // Wt[k*64 + j] = W[j][k]
    __shared__ float Xs[GROWS * XSTRIDE];

    for (int t = threadIdx.x; t < D * D; t += 256) {
        int j = t >> 6, k = t & 63;
        Wt[k * D + j] = W[t];
    }

    const int base = blockIdx.x * GROWS;

    for (int t = threadIdx.x; t < GROWS * 16; t += 256) {
        int r = t >> 4, c4 = (t & 15) << 2;
        int gi = base + r;
        float4 v = make_float4(0.f, 0.f, 0.f, 0.f);
        if (gi < NN) v = *(const float4*)&x[gi * D + c4];
        *(float4*)&Xs[r * XSTRIDE + c4] = v;
    }
    __syncthreads();

    const int cg  = threadIdx.x & 7;
    const int rg  = threadIdx.x >> 3;      // 0..31
    const int col = cg << 3;

    float acc[3][8];
    #pragma unroll
    for (int r = 0; r < 3; r++)
        #pragma unroll
        for (int j = 0; j < 8; j++) acc[r][j] = 0.f;

    #pragma unroll 4
    for (int k4 = 0; k4 < D; k4 += 4) {
        float xr[3][4];
        #pragma unroll
        for (int r = 0; r < 3; r++)
            *(float4*)xr[r] = *(const float4*)&Xs[(rg + 32 * r) * XSTRIDE + k4];
        #pragma unroll
        for (int kk = 0; kk < 4; kk++) {
            float4 w0 = *(const float4*)&Wt[(k4 + kk) * D + col];
            float4 w1 = *(const float4*)&Wt[(k4 + kk) * D + col + 4];
            float wv[8] = {w0.x, w0.y, w0.z, w0.w, w1.x, w1.y, w1.z, w1.w};
            #pragma unroll
            for (int r = 0; r < 3; r++) {
                float xv = xr[r][kk];
                #pragma unroll
                for (int j = 0; j < 8; j++)
                    acc[r][j] = fmaf(xv, wv[j], acc[r][j]);
            }
        }
    }

    #pragma unroll
    for (int r = 0; r < 3; r++) {
        int gi = base + rg + 32 * r;
        if (gi >= NN) continue;
        float s  = g_dis[gi];
        float ss = s * s;
        float4 h0 = make_float4(acc[r][0], acc[r][1], acc[r][2], acc[r][3]);
        float4 h1 = make_float4(acc[r][4], acc[r][5], acc[r][6], acc[r][7]);
        *(float4*)&g_h[gi * D + col]     = h0;
        *(float4*)&g_h[gi * D + col + 4] = h1;
        float4 o0 = make_float4(ss * h0.x, ss * h0.y, ss * h0.z, ss * h0.w);
        float4 o1 = make_float4(ss * h1.x, ss * h1.y, ss * h1.z, ss * h1.w);
        *(float4*)&out[gi * D + col]     = o0;
        *(float4*)&out[gi * D + col + 4] = o1;
    }
}

// ---------------------------------------------------------------------------
// Edge scatter: out[dst] += dis[src]*ew*dis[dst] * h[src].
// 8 threads per edge, each handles 8 floats (2 x red.v4).
// The norm inputs are the same address across the 8-thread group -> one L1
// wavefront each (broadcast), so recomputing norm per thread is ~free.
__global__ __launch_bounds__(256) void k_msg(const int* __restrict__ src,
                                             const int* __restrict__ dst,
                                             const float* __restrict__ ew,
                                             float* __restrict__ out) {
    long long t = (long long)blockIdx.x * blockDim.x + threadIdx.x;
    int e = (int)(t >> 3);
    if (e >= NE) return;
    int c = (int)(t & 7) << 3;     // 0,8,...,56

    int r  = src[e];
    int cl = dst[e];
    float norm = g_dis[r] * ew[e] * g_dis[cl];

    float4 h0 = *(const float4*)&g_h[r * D + c];
    float4 h1 = *(const float4*)&g_h[r * D + c + 4];

    float* p = &out[cl * D + c];
    asm volatile("red.global.add.v4.f32 [%0], {%1, %2, %3, %4};"
                 :: "l"(p),
                    "f"(norm * h0.x), "f"(norm * h0.y),
                    "f"(norm * h0.z), "f"(norm * h0.w)
                 : "memory");
    asm volatile("red.global.add.v4.f32 [%0], {%1, %2, %3, %4};"
                 :: "l"(p + 4),
                    "f"(norm * h1.x), "f"(norm * h1.y),
                    "f"(norm * h1.z), "f"(norm * h1.w)
                 : "memory");
}

// ---------------------------------------------------------------------------
__global__ void k_final(float* __restrict__ out, const float* __restrict__ b) {
    int t = blockIdx.x * blockDim.x + threadIdx.x;   // one float4 per thread
    if (t < NN * (D / 4)) {
        int c = (t & 15) << 2;
        float4 v = *(float4*)&out[t * 4];
        v.x = fmaxf(v.x + __ldg(&b[c + 0]), 0.f);
        v.y = fmaxf(v.y + __ldg(&b[c + 1]), 0.f);
        v.z = fmaxf(v.z + __ldg(&b[c + 2]), 0.f);
        v.w = fmaxf(v.w + __ldg(&b[c + 3]), 0.f);
        *(float4*)&out[t * 4] = v;
    }
}

// ---------------------------------------------------------------------------
extern "C" void kernel_launch(void* const* d_in, const int* in_sizes, int n_in,
                              void* d_out, int out_size) {
    const float* x  = (const float*)d_in[0];
    const int*   ei = (const int*)d_in[1];     // [2, NE] row-major
    const float* ea = (const float*)d_in[2];
    const float* W  = (const float*)d_in[3];
    const float* b  = (const float*)d_in[4];
    float* out = (float*)d_out;

    const int* src = ei;
    const int* dst = ei + NE;

    k_init_deg<<<(NN + 255) / 256, 256>>>();
    k_deg<<<(NE + 255) / 256, 256>>>(dst, ea);
    k_rsqrt<<<(NN + 255) / 256, 256>>>();
    k_gemm<<<(NN + GROWS - 1) / GROWS, 256>>>(x, W, out);
    {
        long long threads = (long long)NE * 8;
        int blocks = (int)((threads + 255) / 256);
        k_msg<<<blocks, 256>>>(src, dst, ea, out);
    }
    k_final<<<(NN * (D / 4) + 255) / 256, 256>>>(out, b);
}

// round 5
// speedup vs baseline: 1.4051x; 1.4051x over previous
#include <cuda_runtime.h>
#include <cuda_fp16.h>

#define NN 100000
#define NE 1200000
#define D  64

// Scratch (device globals — no allocation allowed)
__device__ float   g_dis[NN];          // degree, then rsqrt(degree)
__device__ __half2 g_h[NN * D / 2];    // h = x @ W^T, fp16 (gather-side traffic /2)

// ---------------------------------------------------------------------------
__global__ void k_init_deg() {
    int i = blockIdx.x * blockDim.x + threadIdx.x;
    if (i < NN) g_dis[i] = 1.0f;   // self-loop weight
}

__global__ void k_deg(const int* __restrict__ dst, const float* __restrict__ ew) {
    int e = blockIdx.x * blockDim.x + threadIdx.x;
    if (e < NE) atomicAdd(&g_dis[dst[e]], ew[e]);
}

__global__ void k_rsqrt() {
    int i = blockIdx.x * blockDim.x + threadIdx.x;
    if (i < NN) g_dis[i] = rsqrtf(g_dis[i]);
}

// ---------------------------------------------------------------------------
// GEMM h = x @ W^T fused with self-loop term (out = dis^2 * h)  [R2 layout]
// 256 threads, 128 rows/block, thread = 4 rows x 8 cols micro-tile.
#define GROWS 128
__global__ __launch_bounds__(256) void k_gemm(const float* __restrict__ x,
                                              const float* __restrict__ W,
                                              float* __restrict__ out) {
    __shared__ float Wt[D * D];          // Wt[k*64 + j] = W[j][k]
    __shared__ float Xs[GROWS * 65];     // padded: 65 words/row

    for (int t = threadIdx.x; t < D * D; t += 256) {
        int j = t >> 6, k = t & 63;
        Wt[k * D + j] = W[t];
    }

    const int base = blockIdx.x * GROWS;

    for (int t = threadIdx.x; t < GROWS * 16; t += 256) {
        int r = t >> 4, c4 = (t & 15) << 2;
        int gi = base + r;
        float4 v = make_float4(0.f, 0.f, 0.f, 0.f);
        if (gi < NN) v = *(const float4*)&x[gi * D + c4];
        Xs[r * 65 + c4 + 0] = v.x;
        Xs[r * 65 + c4 + 1] = v.y;
        Xs[r * 65 + c4 + 2] = v.z;
        Xs[r * 65 + c4 + 3] = v.w;
    }
    __syncthreads();

    const int cg = threadIdx.x & 7;      // col group: cols [8*cg, 8*cg+8)
    const int rg = threadIdx.x >> 3;     // row group: rows rg*4 .. rg*4+3
    const int col = cg << 3;

    float acc[4][8];
    #pragma unroll
    for (int r = 0; r < 4; r++)
        #pragma unroll
        for (int j = 0; j < 8; j++) acc[r][j] = 0.f;

    #pragma unroll 4
    for (int k = 0; k < D; k++) {
        float4 w0 = *(const float4*)&Wt[k * D + col];
        float4 w1 = *(const float4*)&Wt[k * D + col + 4];
        float wv[8] = {w0.x, w0.y, w0.z, w0.w, w1.x, w1.y, w1.z, w1.w};
        #pragma unroll
        for (int r = 0; r < 4; r++) {
            float xv = Xs[(rg * 4 + r) * 65 + k];
            #pragma unroll
            for (int j = 0; j < 8; j++)
                acc[r][j] = fmaf(xv, wv[j], acc[r][j]);
        }
    }

    #pragma unroll
    for (int r = 0; r < 4; r++) {
        int gi = base + rg * 4 + r;
        if (gi >= NN) continue;
        float s  = g_dis[gi];
        float ss = s * s;
        // fp16 h for the scatter gather (16B store of 8 halves)
        __half2 hh[4];
        hh[0] = __floats2half2_rn(acc[r][0], acc[r][1]);
        hh[1] = __floats2half2_rn(acc[r][2], acc[r][3]);
        hh[2] = __floats2half2_rn(acc[r][4], acc[r][5]);
        hh[3] = __floats2half2_rn(acc[r][6], acc[r][7]);
        *(uint4*)&g_h[(gi * D + col) >> 1] = *(uint4*)hh;
        // self-loop contribution in full f32
        float4 o0 = make_float4(ss * acc[r][0], ss * acc[r][1],
                                ss * acc[r][2], ss * acc[r][3]);
        float4 o1 = make_float4(ss * acc[r][4], ss * acc[r][5],
                                ss * acc[r][6], ss * acc[r][7]);
        *(float4*)&out[gi * D + col]     = o0;
        *(float4*)&out[gi * D + col + 4] = o1;
    }
}

// ---------------------------------------------------------------------------
// Edge scatter: out[dst] += dis[src]*ew*dis[dst] * h[src]  [R2 layout]
// 16 threads per edge, each handles 4 cols: 8B fp16 gather + one red.v4.f32.
__global__ __launch_bounds__(256) void k_msg(const int* __restrict__ src,
                                             const int* __restrict__ dst,
                                             const float* __restrict__ ew,
                                             float* __restrict__ out) {
    long long t = (long long)blockIdx.x * blockDim.x + threadIdx.x;
    int e = (int)(t >> 4);
    if (e >= NE) return;
    int c = (int)(t & 15) << 2;

    int r  = src[e];
    int cl = dst[e];
    float norm = g_dis[r] * ew[e] * g_dis[cl];

    uint2 raw = *(const uint2*)&g_h[(r * D + c) >> 1];
    __half2 ha = *(__half2*)&raw.x;
    __half2 hb = *(__half2*)&raw.y;
    float2 f0 = __half22float2(ha);
    float2 f1 = __half22float2(hb);

    float* p = &out[cl * D + c];
    asm volatile("red.global.add.v4.f32 [%0], {%1, %2, %3, %4};"
                 :: "l"(p),
                    "f"(norm * f0.x), "f"(norm * f0.y),
                    "f"(norm * f1.x), "f"(norm * f1.y)
                 : "memory");
}

// ---------------------------------------------------------------------------
__global__ void k_final(float* __restrict__ out, const float* __restrict__ b) {
    int t = blockIdx.x * blockDim.x + threadIdx.x;   // one float4 per thread
    if (t < NN * (D / 4)) {
        int c = (t & 15) << 2;
        float4 v = *(float4*)&out[t * 4];
        v.x = fmaxf(v.x + __ldg(&b[c + 0]), 0.f);
        v.y = fmaxf(v.y + __ldg(&b[c + 1]), 0.f);
        v.z = fmaxf(v.z + __ldg(&b[c + 2]), 0.f);
        v.w = fmaxf(v.w + __ldg(&b[c + 3]), 0.f);
        *(float4*)&out[t * 4] = v;
    }
}

// ---------------------------------------------------------------------------
extern "C" void kernel_launch(void* const* d_in, const int* in_sizes, int n_in,
                              void* d_out, int out_size) {
    const float* x  = (const float*)d_in[0];
    const int*   ei = (const int*)d_in[1];     // [2, NE] row-major
    const float* ea = (const float*)d_in[2];
    const float* W  = (const float*)d_in[3];
    const float* b  = (const float*)d_in[4];
    float* out = (float*)d_out;

    const int* src = ei;
    const int* dst = ei + NE;

    k_init_deg<<<(NN + 255) / 256, 256>>>();
    k_deg<<<(NE + 255) / 256, 256>>>(dst, ea);
    k_rsqrt<<<(NN + 255) / 256, 256>>>();
    k_gemm<<<(NN + GROWS - 1) / GROWS, 256>>>(x, W, out);
    {
        long long threads = (long long)NE * 16;
        int blocks = (int)((threads + 255) / 256);
        k_msg<<<blocks, 256>>>(src, dst, ea, out);
    }
    k_final<<<(NN * (D / 4) + 255) / 256, 256>>>(out, b);
}

// round 6
// speedup vs baseline: 1.7384x; 1.2372x over previous
#include <cuda_runtime.h>
#include <cuda_fp16.h>
#include <cstdint>

#define NN 100000
#define NE 1200000
#define D  64

// Scratch (device globals — no allocation allowed)
__device__ float   g_dis[NN];          // degree, then rsqrt(degree)
__device__ __half2 g_h[NN * D / 2];    // h = x @ W^T, fp16 (gather-side traffic /2)

// ---------------------------------------------------------------------------
__global__ void k_init_deg() {
    int i = blockIdx.x * blockDim.x + threadIdx.x;
    if (i < NN) g_dis[i] = 1.0f;   // self-loop weight
}

__global__ void k_deg(const int* __restrict__ dst, const float* __restrict__ ew) {
    int e = blockIdx.x * blockDim.x + threadIdx.x;
    if (e < NE) atomicAdd(&g_dis[dst[e]], ew[e]);
}

__global__ void k_rsqrt() {
    int i = blockIdx.x * blockDim.x + threadIdx.x;
    if (i < NN) g_dis[i] = rsqrtf(g_dis[i]);
}

// ---------------------------------------------------------------------------
// HMMA GEMM: h = x @ W^T (fp16 in, f32 accum), fused self-loop (out = dis^2*h).
// Block: 256 thr (8 warps), 128 rows. Warp w computes rows [16w,16w+16) x 64 cols.
// B (=W^T col-major == W row-major) fragments resident in registers (loaded once).
#define GROWS 128
#define XST 72            // half-element stride (conflict-free for ldmatrix)
__global__ __launch_bounds__(256) void k_gemm(const float* __restrict__ x,
                                              const float* __restrict__ W,
                                              float* __restrict__ out) {
    __shared__ __half Xh[GROWS * XST];   // x tile, fp16
    __shared__ __half Ws[D * XST];       // W rows, fp16: Ws[n][k] = W[n*64+k]

    const int tid  = threadIdx.x;
    const int lane = tid & 31;
    const int wid  = tid >> 5;
    const int base = blockIdx.x * GROWS;

    // Stage W (one-time): Ws[j][k] = W[j][k]
    for (int t = tid; t < D * D; t += 256) {
        int j = t >> 6, k = t & 63;
        Ws[j * XST + k] = __float2half_rn(W[t]);
    }

    // Stage X tile: f32 global -> fp16 smem (zero-fill past NN)
    for (int t = tid; t < GROWS * 16; t += 256) {
        int r = t >> 4, c4 = (t & 15) << 2;
        int gi = base + r;
        float4 v = make_float4(0.f, 0.f, 0.f, 0.f);
        if (gi < NN) v = *(const float4*)&x[gi * D + c4];
        __half2 h0 = __floats2half2_rn(v.x, v.y);
        __half2 h1 = __floats2half2_rn(v.z, v.w);
        uint2 pk = make_uint2(*(uint32_t*)&h0, *(uint32_t*)&h1);
        *(uint2*)&Xh[r * XST + c4] = pk;
    }
    __syncthreads();

    // --- Load B fragments (resident): b[nb][kc][0..1] ---
    // m16n8k16 B frag: b0 = {B[k0][n],B[k0+1][n]}, b1 = {B[k0+8][n],B[k0+9][n]},
    // n = lane>>2, k0 = 2*(lane&3) (+ kc*16). B[k][n] = W[n][k] -> contiguous in Ws.
    uint32_t bfrag[8][4][2];
    {
        int n  = lane >> 2;
        int k0 = (lane & 3) << 1;
        #pragma unroll
        for (int nb = 0; nb < 8; nb++) {
            const __half* wp = &Ws[(nb * 8 + n) * XST];
            #pragma unroll
            for (int kc = 0; kc < 4; kc++) {
                bfrag[nb][kc][0] = *(const uint32_t*)&wp[kc * 16 + k0];
                bfrag[nb][kc][1] = *(const uint32_t*)&wp[kc * 16 + k0 + 8];
            }
        }
    }

    // --- MMA mainloop: 4 k-chunks x 8 n-blocks ---
    float acc[8][4];
    #pragma unroll
    for (int nb = 0; nb < 8; nb++)
        #pragma unroll
        for (int j = 0; j < 4; j++) acc[nb][j] = 0.f;

    const int wrow = wid * 16;
    // ldmatrix address for this lane (kc-dependent column added in loop):
    // matrices: m0=(r, k), m1=(r+8, k), m2=(r, k+8), m3=(r+8, k+8)
    const int mi = lane >> 3, ri = lane & 7;
    const int arow = wrow + ri + (mi & 1) * 8;
    const int acolb = (mi >> 1) * 8;

    #pragma unroll
    for (int kc = 0; kc < 4; kc++) {
        uint32_t a0, a1, a2, a3;
        uint32_t addr = (uint32_t)__cvta_generic_to_shared(
            &Xh[arow * XST + kc * 16 + acolb]);
        asm volatile("ldmatrix.sync.aligned.m8n8.x4.shared.b16 {%0,%1,%2,%3}, [%4];"
                     : "=r"(a0), "=r"(a1), "=r"(a2), "=r"(a3) : "r"(addr));
        #pragma unroll
        for (int nb = 0; nb < 8; nb++) {
            asm volatile(
                "mma.sync.aligned.m16n8k16.row.col.f32.f16.f16.f32 "
                "{%0,%1,%2,%3}, {%4,%5,%6,%7}, {%8,%9}, {%0,%1,%2,%3};"
                : "+f"(acc[nb][0]), "+f"(acc[nb][1]),
                  "+f"(acc[nb][2]), "+f"(acc[nb][3])
                : "r"(a0), "r"(a1), "r"(a2), "r"(a3),
                  "r"(bfrag[nb][kc][0]), "r"(bfrag[nb][kc][1]));
        }
    }

    // --- Epilogue ---
    // c0,c1 -> row lane>>2, cols 2*(lane&3)+{0,1}; c2,c3 -> row+8.
    const int r0g = base + wrow + (lane >> 2);
    const int r1g = r0g + 8;
    const int cc  = (lane & 3) << 1;
    float ss0 = 0.f, ss1 = 0.f;
    if (r0g < NN) { float s = g_dis[r0g]; ss0 = s * s; }
    if (r1g < NN) { float s = g_dis[r1g]; ss1 = s * s; }

    #pragma unroll
    for (int nb = 0; nb < 8; nb++) {
        int c0 = nb * 8 + cc;
        if (r0g < NN) {
            __half2 hh = __floats2half2_rn(acc[nb][0], acc[nb][1]);
            g_h[(r0g * D + c0) >> 1] = hh;
            *(float2*)&out[r0g * D + c0] =
                make_float2(ss0 * acc[nb][0], ss0 * acc[nb][1]);
        }
        if (r1g < NN) {
            __half2 hh = __floats2half2_rn(acc[nb][2], acc[nb][3]);
            g_h[(r1g * D + c0) >> 1] = hh;
            *(float2*)&out[r1g * D + c0] =
                make_float2(ss1 * acc[nb][2], ss1 * acc[nb][3]);
        }
    }
}

// ---------------------------------------------------------------------------
// Edge scatter: out[dst] += dis[src]*ew*dis[dst] * h[src]
// 16 threads per edge, each handles 4 cols: 8B fp16 gather + one red.v4.f32.
__global__ __launch_bounds__(256) void k_msg(const int* __restrict__ src,
                                             const int* __restrict__ dst,
                                             const float* __restrict__ ew,
                                             float* __restrict__ out) {
    long long t = (long long)blockIdx.x * blockDim.x + threadIdx.x;
    int e = (int)(t >> 4);
    if (e >= NE) return;
    int c = (int)(t & 15) << 2;

    int r  = src[e];
    int cl = dst[e];
    float norm = g_dis[r] * ew[e] * g_dis[cl];

    uint2 raw = *(const uint2*)&g_h[(r * D + c) >> 1];
    __half2 ha = *(__half2*)&raw.x;
    __half2 hb = *(__half2*)&raw.y;
    float2 f0 = __half22float2(ha);
    float2 f1 = __half22float2(hb);

    float* p = &out[cl * D + c];
    asm volatile("red.global.add.v4.f32 [%0], {%1, %2, %3, %4};"
                 :: "l"(p),
                    "f"(norm * f0.x), "f"(norm * f0.y),
                    "f"(norm * f1.x), "f"(norm * f1.y)
                 : "memory");
}

// ---------------------------------------------------------------------------
__global__ void k_final(float* __restrict__ out, const float* __restrict__ b) {
    int t = blockIdx.x * blockDim.x + threadIdx.x;   // one float4 per thread
    if (t < NN * (D / 4)) {
        int c = (t & 15) << 2;
        float4 v = *(float4*)&out[t * 4];
        v.x = fmaxf(v.x + __ldg(&b[c + 0]), 0.f);
        v.y = fmaxf(v.y + __ldg(&b[c + 1]), 0.f);
        v.z = fmaxf(v.z + __ldg(&b[c + 2]), 0.f);
        v.w = fmaxf(v.w + __ldg(&b[c + 3]), 0.f);
        *(float4*)&out[t * 4] = v;
    }
}

// ---------------------------------------------------------------------------
extern "C" void kernel_launch(void* const* d_in, const int* in_sizes, int n_in,
                              void* d_out, int out_size) {
    const float* x  = (const float*)d_in[0];
    const int*   ei = (const int*)d_in[1];     // [2, NE] row-major
    const float* ea = (const float*)d_in[2];
    const float* W  = (const float*)d_in[3];
    const float* b  = (const float*)d_in[4];
    float* out = (float*)d_out;

    const int* src = ei;
    const int* dst = ei + NE;

    k_init_deg<<<(NN + 255) / 256, 256>>>();
    k_deg<<<(NE + 255) / 256, 256>>>(dst, ea);
    k_rsqrt<<<(NN + 255) / 256, 256>>>();
    k_gemm<<<(NN + GROWS - 1) / GROWS, 256>>>(x, W, out);
    {
        long long threads = (long long)NE * 16;
        int blocks = (int)((threads + 255) / 256);
        k_msg<<<blocks, 256>>>(src, dst, ea, out);
    }
    k_final<<<(NN * (D / 4) + 255) / 256, 256>>>(out, b);
}

// round 7
// speedup vs baseline: 1.8659x; 1.0733x over previous
#include <cuda_runtime.h>
#include <cuda_fp16.h>
#include <cstdint>

#define NN 100000
#define NE 1200000
#define D  64
#define SCAN_B 1024
#define NB ((NN + SCAN_B - 1) / SCAN_B)   // 98

// Scratch (device globals — no allocation allowed)
__device__ float   g_dis[NN];          // degree, then rsqrt(degree)
__device__ __half2 g_h[NN * D / 2];    // h = x @ W^T, fp16
__device__ int     g_cnt[NN];          // per-dst in-degree (int)
__device__ int     g_off[NN + 1];      // CSR offsets
__device__ int     g_cur[NN];          // fill cursors
__device__ int     g_bsum[128];        // scan block sums
__device__ int2    g_pack[NE];         // {src, bits(dis[src]*ew)}

// ---------------------------------------------------------------------------
__global__ void k_init() {
    int i = blockIdx.x * blockDim.x + threadIdx.x;
    if (i < NN) { g_dis[i] = 1.0f; g_cnt[i] = 0; }   // self-loop weight 1
}

// degree (float, weighted) + count (int) in one pass
__global__ void k_deg(const int* __restrict__ dst, const float* __restrict__ ew) {
    int e = blockIdx.x * blockDim.x + threadIdx.x;
    if (e < NE) {
        int d = dst[e];
        atomicAdd(&g_dis[d], ew[e]);
        atomicAdd(&g_cnt[d], 1);
    }
}

__global__ void k_rsqrt() {
    int i = blockIdx.x * blockDim.x + threadIdx.x;
    if (i < NN) g_dis[i] = rsqrtf(g_dis[i]);
}

// ---------------------------------------------------------------------------
// 3-kernel exclusive scan of g_cnt -> g_off
__global__ void k_scan1() {
    __shared__ int s[SCAN_B];
    int i = blockIdx.x * SCAN_B + threadIdx.x;
    int v = (i < NN) ? g_cnt[i] : 0;
    s[threadIdx.x] = v;
    for (int d = 1; d < SCAN_B; d <<= 1) {
        __syncthreads();
        int t = (threadIdx.x >= d) ? s[threadIdx.x - d] : 0;
        __syncthreads();
        s[threadIdx.x] += t;
    }
    __syncthreads();
    if (i < NN) g_off[i] = s[threadIdx.x] - v;          // exclusive, pre-blocksum
    if (threadIdx.x == SCAN_B - 1) g_bsum[blockIdx.x] = s[SCAN_B - 1];
}

__global__ void k_scan2() {
    __shared__ int s[128];
    int t = threadIdx.x;
    int v = (t < NB) ? g_bsum[t] : 0;
    s[t] = v;
    for (int d = 1; d < 128; d <<= 1) {
        __syncthreads();
        int u = (t >= d) ? s[t - d] : 0;
        __syncthreads();
        s[t] += u;
    }
    __syncthreads();
    if (t < NB) g_bsum[t] = s[t] - v;                   // exclusive block base
}

__global__ void k_scan3() {
    int i = blockIdx.x * SCAN_B + threadIdx.x;
    if (i < NN) {
        int o = g_off[i] + g_bsum[blockIdx.x];
        g_off[i] = o;
        g_cur[i] = o;
    }
    if (i == 0) g_off[NN] = NE;
}

// ---------------------------------------------------------------------------
// Fill CSR: pack {src, dis[src]*ew} into dst-grouped segments
__global__ void k_fill(const int* __restrict__ src, const int* __restrict__ dst,
                       const float* __restrict__ ew) {
    int e = blockIdx.x * blockDim.x + threadIdx.x;
    if (e >= NE) return;
    int s = src[e], d = dst[e];
    int pos = atomicAdd(&g_cur[d], 1);
    float m = g_dis[s] * ew[e];
    g_pack[pos] = make_int2(s, __float_as_int(m));
}

// ---------------------------------------------------------------------------
// HMMA GEMM: h = x @ W^T (fp16 in, f32 accum), fused self-loop (out = dis^2*h).
#define GROWS 128
#define XST 72
__global__ __launch_bounds__(256) void k_gemm(const float* __restrict__ x,
                                              const float* __restrict__ W,
                                              float* __restrict__ out) {
    __shared__ __half Xh[GROWS * XST];
    __shared__ __half Ws[D * XST];

    const int tid  = threadIdx.x;
    const int lane = tid & 31;
    const int wid  = tid >> 5;
    const int base = blockIdx.x * GROWS;

    for (int t = tid; t < D * D; t += 256) {
        int j = t >> 6, k = t & 63;
        Ws[j * XST + k] = __float2half_rn(W[t]);
    }
    for (int t = tid; t < GROWS * 16; t += 256) {
        int r = t >> 4, c4 = (t & 15) << 2;
        int gi = base + r;
        float4 v = make_float4(0.f, 0.f, 0.f, 0.f);
        if (gi < NN) v = *(const float4*)&x[gi * D + c4];
        __half2 h0 = __floats2half2_rn(v.x, v.y);
        __half2 h1 = __floats2half2_rn(v.z, v.w);
        uint2 pk = make_uint2(*(uint32_t*)&h0, *(uint32_t*)&h1);
        *(uint2*)&Xh[r * XST + c4] = pk;
    }
    __syncthreads();

    uint32_t bfrag[8][4][2];
    {
        int n  = lane >> 2;
        int k0 = (lane & 3) << 1;
        #pragma unroll
        for (int nb = 0; nb < 8; nb++) {
            const __half* wp = &Ws[(nb * 8 + n) * XST];
            #pragma unroll
            for (int kc = 0; kc < 4; kc++) {
                bfrag[nb][kc][0] = *(const uint32_t*)&wp[kc * 16 + k0];
                bfrag[nb][kc][1] = *(const uint32_t*)&wp[kc * 16 + k0 + 8];
            }
        }
    }

    float acc[8][4];
    #pragma unroll
    for (int nb = 0; nb < 8; nb++)
        #pragma unroll
        for (int j = 0; j < 4; j++) acc[nb][j] = 0.f;

    const int wrow = wid * 16;
    const int mi = lane >> 3, ri = lane & 7;
    const int arow = wrow + ri + (mi & 1) * 8;
    const int acolb = (mi >> 1) * 8;

    #pragma unroll
    for (int kc = 0; kc < 4; kc++) {
        uint32_t a0, a1, a2, a3;
        uint32_t addr = (uint32_t)__cvta_generic_to_shared(
            &Xh[arow * XST + kc * 16 + acolb]);
        asm volatile("ldmatrix.sync.aligned.m8n8.x4.shared.b16 {%0,%1,%2,%3}, [%4];"
                     : "=r"(a0), "=r"(a1), "=r"(a2), "=r"(a3) : "r"(addr));
        #pragma unroll
        for (int nb = 0; nb < 8; nb++) {
            asm volatile(
                "mma.sync.aligned.m16n8k16.row.col.f32.f16.f16.f32 "
                "{%0,%1,%2,%3}, {%4,%5,%6,%7}, {%8,%9}, {%0,%1,%2,%3};"
                : "+f"(acc[nb][0]), "+f"(acc[nb][1]),
                  "+f"(acc[nb][2]), "+f"(acc[nb][3])
                : "r"(a0), "r"(a1), "r"(a2), "r"(a3),
                  "r"(bfrag[nb][kc][0]), "r"(bfrag[nb][kc][1]));
        }
    }

    const int r0g = base + wrow + (lane >> 2);
    const int r1g = r0g + 8;
    const int cc  = (lane & 3) << 1;
    float ss0 = 0.f, ss1 = 0.f;
    if (r0g < NN) { float s = g_dis[r0g]; ss0 = s * s; }
    if (r1g < NN) { float s = g_dis[r1g]; ss1 = s * s; }

    #pragma unroll
    for (int nb = 0; nb < 8; nb++) {
        int c0 = nb * 8 + cc;
        if (r0g < NN) {
            g_h[(r0g * D + c0) >> 1] = __floats2half2_rn(acc[nb][0], acc[nb][1]);
            *(float2*)&out[r0g * D + c0] =
                make_float2(ss0 * acc[nb][0], ss0 * acc[nb][1]);
        }
        if (r1g < NN) {
            g_h[(r1g * D + c0) >> 1] = __floats2half2_rn(acc[nb][2], acc[nb][3]);
            *(float2*)&out[r1g * D + c0] =
                make_float2(ss1 * acc[nb][2], ss1 * acc[nb][3]);
        }
    }
}

// ---------------------------------------------------------------------------
// Aggregate (gather form): warp per dst node.
// out[d] = relu( out_init[d] + dis[d] * sum_e m_e * h[src_e] + b )
__global__ __launch_bounds__(256) void k_aggr(const float* __restrict__ b,
                                              float* __restrict__ out) {
    int gw   = (blockIdx.x * 256 + threadIdx.x) >> 5;   // one dst per warp
    int lane = threadIdx.x & 31;
    if (gw >= NN) return;

    int off = g_off[gw];
    int end = g_off[gw + 1];

    float2 acc = make_float2(0.f, 0.f);
    for (int eb = off; eb < end; eb += 32) {
        int n = min(32, end - eb);
        int2 pk = make_int2(0, 0);
        if (lane < n) pk = g_pack[eb + lane];
        for (int j = 0; j < n; j++) {
            int   sj = __shfl_sync(0xffffffffu, pk.x, j);
            float mj = __int_as_float(__shfl_sync(0xffffffffu, pk.y, j));
            float2 f = __half22float2(g_h[sj * (D / 2) + lane]);
            acc.x = fmaf(mj, f.x, acc.x);
            acc.y = fmaf(mj, f.y, acc.y);
        }
    }

    float dd = g_dis[gw];
    float2 o  = *(float2*)&out[gw * D + 2 * lane];
    float2 bb = *(const float2*)&b[2 * lane];
    o.x = fmaxf(fmaf(dd, acc.x, o.x) + bb.x, 0.f);
    o.y = fmaxf(fmaf(dd, acc.y, o.y) + bb.y, 0.f);
    *(float2*)&out[gw * D + 2 * lane] = o;
}

// ---------------------------------------------------------------------------
extern "C" void kernel_launch(void* const* d_in, const int* in_sizes, int n_in,
                              void* d_out, int out_size) {
    const float* x  = (const float*)d_in[0];
    const int*   ei = (const int*)d_in[1];     // [2, NE] row-major
    const float* ea = (const float*)d_in[2];
    const float* W  = (const float*)d_in[3];
    const float* b  = (const float*)d_in[4];
    float* out = (float*)d_out;

    const int* src = ei;
    const int* dst = ei + NE;

    k_init<<<(NN + 255) / 256, 256>>>();
    k_deg<<<(NE + 255) / 256, 256>>>(dst, ea);
    k_rsqrt<<<(NN + 255) / 256, 256>>>();
    k_scan1<<<NB, SCAN_B>>>();
    k_scan2<<<1, 128>>>();
    k_scan3<<<NB, SCAN_B>>>();
    k_fill<<<(NE + 255) / 256, 256>>>(src, dst, ea);
    k_gemm<<<(NN + GROWS - 1) / GROWS, 256>>>(x, W, out);
    k_aggr<<<(NN * 32 + 255) / 256, 256>>>(b, out);
}

// round 8
// speedup vs baseline: 2.0342x; 1.0902x over previous
#include <cuda_runtime.h>
#include <cuda_fp16.h>
#include <cstdint>

#define NN 100000
#define NE 1200000
#define D  64
#define SCAN_B 1024
#define NB ((NN + SCAN_B - 1) / SCAN_B)   // 98

// Scratch (device globals — no allocation allowed)
__device__ float   g_dis[NN];          // degree, then rsqrt(degree)
__device__ __half2 g_h[NN * D / 2];    // h = x @ W^T, fp16
__device__ int     g_cnt[NN];          // per-dst in-degree (int)
__device__ int     g_off[NN + 1];      // CSR offsets
__device__ int     g_cur[NN];          // fill cursors
__device__ int     g_bsum[128];        // scan block sums
__device__ int2    g_pack[NE];         // {src, bits(dis[src]*ew)}

// ---------------------------------------------------------------------------
__global__ void k_init() {
    int i = blockIdx.x * blockDim.x + threadIdx.x;
    if (i < NN) { g_dis[i] = 1.0f; g_cnt[i] = 0; }   // self-loop weight 1
}

// degree (float, weighted) + count (int) in one pass
__global__ void k_deg(const int* __restrict__ dst, const float* __restrict__ ew) {
    int e = blockIdx.x * blockDim.x + threadIdx.x;
    if (e < NE) {
        int d = dst[e];
        atomicAdd(&g_dis[d], ew[e]);
        atomicAdd(&g_cnt[d], 1);
    }
}

// ---------------------------------------------------------------------------
// Scan stage 1 (warp-shuffle) + fused rsqrt of the degree array.
__global__ void k_scan1() {
    __shared__ int wsum[32];
    int i = blockIdx.x * SCAN_B + threadIdx.x;
    int lane = threadIdx.x & 31, w = threadIdx.x >> 5;
    int v = (i < NN) ? g_cnt[i] : 0;
    int s = v;
    #pragma unroll
    for (int d = 1; d < 32; d <<= 1) {
        int t = __shfl_up_sync(0xffffffffu, s, d);
        if (lane >= d) s += t;
    }
    if (lane == 31) wsum[w] = s;
    __syncthreads();
    if (w == 0) {
        int t = wsum[lane];
        #pragma unroll
        for (int d = 1; d < 32; d <<= 1) {
            int u = __shfl_up_sync(0xffffffffu, t, d);
            if (lane >= d) t += u;
        }
        wsum[lane] = t;                        // inclusive warp sums
    }
    __syncthreads();
    int base = (w > 0) ? wsum[w - 1] : 0;
    int incl = s + base;
    if (i < NN) g_off[i] = incl - v;           // exclusive, pre-blocksum
    if (threadIdx.x == SCAN_B - 1) g_bsum[blockIdx.x] = incl;
    // fused: dis = rsqrt(deg)
    if (i < NN) g_dis[i] = rsqrtf(g_dis[i]);
}

__global__ void k_scan2() {    // 128 threads, 4 warps
    __shared__ int wsum[4];
    int t = threadIdx.x;
    int lane = t & 31, w = t >> 5;
    int v = (t < NB) ? g_bsum[t] : 0;
    int s = v;
    #pragma unroll
    for (int d = 1; d < 32; d <<= 1) {
        int u = __shfl_up_sync(0xffffffffu, s, d);
        if (lane >= d) s += u;
    }
    if (lane == 31) wsum[w] = s;
    __syncthreads();
    int base = 0;
    for (int k = 0; k < w; k++) base += wsum[k];
    if (t < NB) g_bsum[t] = s + base - v;      // exclusive block base
}

__global__ void k_scan3() {
    int i = blockIdx.x * SCAN_B + threadIdx.x;
    if (i < NN) {
        int o = g_off[i] + g_bsum[blockIdx.x];
        g_off[i] = o;
        g_cur[i] = o;
    }
    if (i == 0) g_off[NN] = NE;
}

// ---------------------------------------------------------------------------
// Fill CSR: pack {src, dis[src]*ew} into dst-grouped segments
__global__ void k_fill(const int* __restrict__ src, const int* __restrict__ dst,
                       const float* __restrict__ ew) {
    int e = blockIdx.x * blockDim.x + threadIdx.x;
    if (e >= NE) return;
    int s = src[e], d = dst[e];
    int pos = atomicAdd(&g_cur[d], 1);
    float m = g_dis[s] * ew[e];
    g_pack[pos] = make_int2(s, __float_as_int(m));
}

// ---------------------------------------------------------------------------
// HMMA GEMM: h = x @ W^T (fp16 in, f32 accum). Writes fp16 g_h ONLY
// (self-loop term is applied in k_aggr from g_h).
#define GROWS 128
#define XST 72
__global__ __launch_bounds__(256) void k_gemm(const float* __restrict__ x,
                                              const float* __restrict__ W) {
    __shared__ __half Xh[GROWS * XST];
    __shared__ __half Ws[D * XST];

    const int tid  = threadIdx.x;
    const int lane = tid & 31;
    const int wid  = tid >> 5;
    const int base = blockIdx.x * GROWS;

    for (int t = tid; t < D * D; t += 256) {
        int j = t >> 6, k = t & 63;
        Ws[j * XST + k] = __float2half_rn(W[t]);
    }
    for (int t = tid; t < GROWS * 16; t += 256) {
        int r = t >> 4, c4 = (t & 15) << 2;
        int gi = base + r;
        float4 v = make_float4(0.f, 0.f, 0.f, 0.f);
        if (gi < NN) v = *(const float4*)&x[gi * D + c4];
        __half2 h0 = __floats2half2_rn(v.x, v.y);
        __half2 h1 = __floats2half2_rn(v.z, v.w);
        uint2 pk = make_uint2(*(uint32_t*)&h0, *(uint32_t*)&h1);
        *(uint2*)&Xh[r * XST + c4] = pk;
    }
    __syncthreads();

    uint32_t bfrag[8][4][2];
    {
        int n  = lane >> 2;
        int k0 = (lane & 3) << 1;
        #pragma unroll
        for (int nb = 0; nb < 8; nb++) {
            const __half* wp = &Ws[(nb * 8 + n) * XST];
            #pragma unroll
            for (int kc = 0; kc < 4; kc++) {
                bfrag[nb][kc][0] = *(const uint32_t*)&wp[kc * 16 + k0];
                bfrag[nb][kc][1] = *(const uint32_t*)&wp[kc * 16 + k0 + 8];
            }
        }
    }

    float acc[8][4];
    #pragma unroll
    for (int nb = 0; nb < 8; nb++)
        #pragma unroll
        for (int j = 0; j < 4; j++) acc[nb][j] = 0.f;

    const int wrow = wid * 16;
    const int mi = lane >> 3, ri = lane & 7;
    const int arow = wrow + ri + (mi & 1) * 8;
    const int acolb = (mi >> 1) * 8;

    #pragma unroll
    for (int kc = 0; kc < 4; kc++) {
        uint32_t a0, a1, a2, a3;
        uint32_t addr = (uint32_t)__cvta_generic_to_shared(
            &Xh[arow * XST + kc * 16 + acolb]);
        asm volatile("ldmatrix.sync.aligned.m8n8.x4.shared.b16 {%0,%1,%2,%3}, [%4];"
                     : "=r"(a0), "=r"(a1), "=r"(a2), "=r"(a3) : "r"(addr));
        #pragma unroll
        for (int nb = 0; nb < 8; nb++) {
            asm volatile(
                "mma.sync.aligned.m16n8k16.row.col.f32.f16.f16.f32 "
                "{%0,%1,%2,%3}, {%4,%5,%6,%7}, {%8,%9}, {%0,%1,%2,%3};"
                : "+f"(acc[nb][0]), "+f"(acc[nb][1]),
                  "+f"(acc[nb][2]), "+f"(acc[nb][3])
                : "r"(a0), "r"(a1), "r"(a2), "r"(a3),
                  "r"(bfrag[nb][kc][0]), "r"(bfrag[nb][kc][1]));
        }
    }

    const int r0g = base + wrow + (lane >> 2);
    const int r1g = r0g + 8;
    const int cc  = (lane & 3) << 1;

    #pragma unroll
    for (int nb = 0; nb < 8; nb++) {
        int c0 = nb * 8 + cc;
        if (r0g < NN)
            g_h[(r0g * D + c0) >> 1] = __floats2half2_rn(acc[nb][0], acc[nb][1]);
        if (r1g < NN)
            g_h[(r1g * D + c0) >> 1] = __floats2half2_rn(acc[nb][2], acc[nb][3]);
    }
}

// ---------------------------------------------------------------------------
// Aggregate (gather form): warp per dst node, unroll x4 for MLP.
// out[d] = relu( dis[d] * ( dis[d]*h[d] + sum_e m_e*h[src_e] ) + b )
__global__ __launch_bounds__(256) void k_aggr(const float* __restrict__ b,
                                              float* __restrict__ out) {
    int gw   = (blockIdx.x * 256 + threadIdx.x) >> 5;   // one dst per warp
    int lane = threadIdx.x & 31;
    if (gw >= NN) return;

    int off = g_off[gw];
    int end = g_off[gw + 1];
    float dd = g_dis[gw];

    // self-loop seed: dis*h[d]
    float2 hd = __half22float2(g_h[gw * (D / 2) + lane]);
    float2 acc = make_float2(dd * hd.x, dd * hd.y);

    for (int eb = off; eb < end; eb += 32) {
        int n = min(32, end - eb);
        int2 pk = make_int2(0, 0);
        if (lane < n) pk = g_pack[eb + lane];
        int j = 0;
        for (; j + 4 <= n; j += 4) {
            int   s0 = __shfl_sync(0xffffffffu, pk.x, j);
            int   s1 = __shfl_sync(0xffffffffu, pk.x, j + 1);
            int   s2 = __shfl_sync(0xffffffffu, pk.x, j + 2);
            int   s3 = __shfl_sync(0xffffffffu, pk.x, j + 3);
            float m0 = __int_as_float(__shfl_sync(0xffffffffu, pk.y, j));
            float m1 = __int_as_float(__shfl_sync(0xffffffffu, pk.y, j + 1));
            float m2 = __int_as_float(__shfl_sync(0xffffffffu, pk.y, j + 2));
            float m3 = __int_as_float(__shfl_sync(0xffffffffu, pk.y, j + 3));
            __half2 r0 = g_h[s0 * (D / 2) + lane];
            __half2 r1 = g_h[s1 * (D / 2) + lane];
            __half2 r2 = g_h[s2 * (D / 2) + lane];
            __half2 r3 = g_h[s3 * (D / 2) + lane];
            float2 f0 = __half22float2(r0);
            float2 f1 = __half22float2(r1);
            float2 f2 = __half22float2(r2);
            float2 f3 = __half22float2(r3);
            acc.x = fmaf(m0, f0.x, acc.x); acc.y = fmaf(m0, f0.y, acc.y);
            acc.x = fmaf(m1, f1.x, acc.x); acc.y = fmaf(m1, f1.y, acc.y);
            acc.x = fmaf(m2, f2.x, acc.x); acc.y = fmaf(m2, f2.y, acc.y);
            acc.x = fmaf(m3, f3.x, acc.x); acc.y = fmaf(m3, f3.y, acc.y);
        }
        for (; j < n; j++) {
            int   sj = __shfl_sync(0xffffffffu, pk.x, j);
            float mj = __int_as_float(__shfl_sync(0xffffffffu, pk.y, j));
            float2 f = __half22float2(g_h[sj * (D / 2) + lane]);
            acc.x = fmaf(mj, f.x, acc.x);
            acc.y = fmaf(mj, f.y, acc.y);
        }
    }

    float2 bb = *(const float2*)&b[2 * lane];
    float2 o;
    o.x = fmaxf(fmaf(dd, acc.x, bb.x), 0.f);
    o.y = fmaxf(fmaf(dd, acc.y, bb.y), 0.f);
    *(float2*)&out[gw * D + 2 * lane] = o;
}

// ---------------------------------------------------------------------------
extern "C" void kernel_launch(void* const* d_in, const int* in_sizes, int n_in,
                              void* d_out, int out_size) {
    const float* x  = (const float*)d_in[0];
    const int*   ei = (const int*)d_in[1];     // [2, NE] row-major
    const float* ea = (const float*)d_in[2];
    const float* W  = (const float*)d_in[3];
    const float* b  = (const float*)d_in[4];
    float* out = (float*)d_out;

    const int* src = ei;
    const int* dst = ei + NE;

    k_init<<<(NN + 255) / 256, 256>>>();
    k_deg<<<(NE + 255) / 256, 256>>>(dst, ea);
    k_scan1<<<NB, SCAN_B>>>();                  // + fused rsqrt
    k_scan2<<<1, 128>>>();
    k_scan3<<<NB, SCAN_B>>>();
    k_fill<<<(NE + 255) / 256, 256>>>(src, dst, ea);
    k_gemm<<<(NN + GROWS - 1) / GROWS, 256>>>(x, W);
    k_aggr<<<(NN * 32 + 255) / 256, 256>>>(b, out);
}

// round 9
// speedup vs baseline: 2.2418x; 1.1021x over previous
#include <cuda_runtime.h>
#include <cuda_fp16.h>
#include <cstdint>

#define NN 100000
#define NE 1200000
#define D  64
#define SCAN_B 1024
#define NB ((NN + SCAN_B - 1) / SCAN_B)   // 98

// Scratch (device globals — no allocation allowed)
__device__ float              g_dis[NN];      // rsqrt(degree)
__device__ __half2            g_h[NN * D / 2];
__device__ unsigned long long g_pk64[NN];     // hi: count, lo: fixed-point wdeg
__device__ int                g_off[NN + 1];  // CSR offsets
__device__ int                g_cur[NN];      // fill cursors
__device__ int                g_bsum[128];    // scan block sums
__device__ int2               g_pack[NE];     // {src, bits(dis[src]*ew)}

// ---------------------------------------------------------------------------
__global__ void k_init() {
    int i = blockIdx.x * blockDim.x + threadIdx.x;
    if (i < NN) g_pk64[i] = 0ULL;
}

// one packed 64-bit atomic per edge: count + fixed-point weighted degree
__global__ void k_deg(const int* __restrict__ dst, const float* __restrict__ ew) {
    int e = blockIdx.x * blockDim.x + threadIdx.x;
    if (e < NE) {
        unsigned int q = __float2uint_rn(ew[e] * 16777216.0f);
        unsigned long long inc = (1ULL << 32) | (unsigned long long)q;
        atomicAdd(&g_pk64[dst[e]], inc);
    }
}

// ---------------------------------------------------------------------------
// Scan stage 1 (warp-shuffle over counts) + fused dis = rsqrt(deg).
__global__ void k_scan1() {
    __shared__ int wsum[32];
    int i = blockIdx.x * SCAN_B + threadIdx.x;
    int lane = threadIdx.x & 31, w = threadIdx.x >> 5;
    unsigned long long p = (i < NN) ? g_pk64[i] : 0ULL;
    int v = (int)(p >> 32);
    int s = v;
    #pragma unroll
    for (int d = 1; d < 32; d <<= 1) {
        int t = __shfl_up_sync(0xffffffffu, s, d);
        if (lane >= d) s += t;
    }
    if (lane == 31) wsum[w] = s;
    __syncthreads();
    if (w == 0) {
        int t = wsum[lane];
        #pragma unroll
        for (int d = 1; d < 32; d <<= 1) {
            int u = __shfl_up_sync(0xffffffffu, t, d);
            if (lane >= d) t += u;
        }
        wsum[lane] = t;
    }
    __syncthreads();
    int base = (w > 0) ? wsum[w - 1] : 0;
    int incl = s + base;
    if (i < NN) {
        g_off[i] = incl - v;               // exclusive, pre-blocksum
        float deg = 1.0f + (float)(unsigned int)p * (1.0f / 16777216.0f);
        g_dis[i] = rsqrtf(deg);
    }
    if (threadIdx.x == SCAN_B - 1) g_bsum[blockIdx.x] = incl;
}

// Scan stage 2+3 fused: each block redundantly scans the 98 block sums.
__global__ void k_scan3() {
    __shared__ int sbase[NB];
    if (threadIdx.x < 32) {
        int lane = threadIdx.x;
        int carry = 0;
        for (int c = 0; c < NB; c += 32) {
            int idx = c + lane;
            int v = (idx < NB) ? g_bsum[idx] : 0;
            int s = v;
            #pragma unroll
            for (int d = 1; d < 32; d <<= 1) {
                int t = __shfl_up_sync(0xffffffffu, s, d);
                if (lane >= d) s += t;
            }
            if (idx < NB) sbase[idx] = carry + s - v;
            carry += __shfl_sync(0xffffffffu, s, 31);
        }
    }
    __syncthreads();
    int i = blockIdx.x * SCAN_B + threadIdx.x;
    if (i < NN) {
        int o = g_off[i] + sbase[blockIdx.x];
        g_off[i] = o;
        g_cur[i] = o;
    }
    if (i == 0) g_off[NN] = NE;
}

// ---------------------------------------------------------------------------
// Fill CSR: pack {src, dis[src]*ew} into dst-grouped segments
__global__ void k_fill(const int* __restrict__ src, const int* __restrict__ dst,
                       const float* __restrict__ ew) {
    int e = blockIdx.x * blockDim.x + threadIdx.x;
    if (e >= NE) return;
    int s = src[e], d = dst[e];
    int pos = atomicAdd(&g_cur[d], 1);
    float m = g_dis[s] * ew[e];
    g_pack[pos] = make_int2(s, __float_as_int(m));
}

// ---------------------------------------------------------------------------
// HMMA GEMM, A direct-from-global: h = x @ W^T (fp16 in, f32 accum) -> g_h.
// 256 thr / 8 warps, warp w: rows [16w,16w+16). A frags loaded as float2 from
// x (32B/sector-aligned per lane quad) and packed to half2 in registers.
#define GROWS 128
#define XST 72
__global__ __launch_bounds__(256) void k_gemm(const float* __restrict__ x,
                                              const float* __restrict__ W) {
    __shared__ __half Ws[D * XST];

    const int tid  = threadIdx.x;
    const int lane = tid & 31;
    const int wid  = tid >> 5;
    const int base = blockIdx.x * GROWS;

    for (int t = tid; t < D * D; t += 256) {
        int j = t >> 6, k = t & 63;
        Ws[j * XST + k] = __float2half_rn(W[t]);
    }
    __syncthreads();

    // B fragments: b0={B[k0][n],B[k0+1][n]}, b1 same +8 k.  B[k][n]=W[n][k].
    uint32_t bfrag[8][4][2];
    {
        int n  = lane >> 2;
        int k0 = (lane & 3) << 1;
        #pragma unroll
        for (int nb = 0; nb < 8; nb++) {
            const __half* wp = &Ws[(nb * 8 + n) * XST];
            #pragma unroll
            for (int kc = 0; kc < 4; kc++) {
                bfrag[nb][kc][0] = *(const uint32_t*)&wp[kc * 16 + k0];
                bfrag[nb][kc][1] = *(const uint32_t*)&wp[kc * 16 + k0 + 8];
            }
        }
    }

    float acc[8][4];
    #pragma unroll
    for (int nb = 0; nb < 8; nb++)
        #pragma unroll
        for (int j = 0; j < 4; j++) acc[nb][j] = 0.f;

    // A fragment rows/cols for this lane (m16n8k16 row-major A):
    // a0: (r0, c), a1: (r1, c), a2: (r0, c+8), a3: (r1, c+8); c = 2*tig + 16*kc
    const int gid = lane >> 2, tig = lane & 3;
    const int r0  = base + wid * 16 + gid;
    const int r1  = r0 + 8;
    const bool v0 = r0 < NN, v1 = r1 < NN;
    const float* xr0 = &x[(size_t)(v0 ? r0 : 0) * D + 2 * tig];
    const float* xr1 = &x[(size_t)(v1 ? r1 : 0) * D + 2 * tig];

    #pragma unroll
    for (int kc = 0; kc < 4; kc++) {
        float2 z = make_float2(0.f, 0.f);
        float2 f00 = v0 ? *(const float2*)&xr0[16 * kc]     : z;
        float2 f10 = v1 ? *(const float2*)&xr1[16 * kc]     : z;
        float2 f01 = v0 ? *(const float2*)&xr0[16 * kc + 8] : z;
        float2 f11 = v1 ? *(const float2*)&xr1[16 * kc + 8] : z;
        __half2 ha0 = __floats2half2_rn(f00.x, f00.y);
        __half2 ha1 = __floats2half2_rn(f10.x, f10.y);
        __half2 ha2 = __floats2half2_rn(f01.x, f01.y);
        __half2 ha3 = __floats2half2_rn(f11.x, f11.y);
        uint32_t a0 = *(uint32_t*)&ha0, a1 = *(uint32_t*)&ha1;
        uint32_t a2 = *(uint32_t*)&ha2, a3 = *(uint32_t*)&ha3;
        #pragma unroll
        for (int nb = 0; nb < 8; nb++) {
            asm volatile(
                "mma.sync.aligned.m16n8k16.row.col.f32.f16.f16.f32 "
                "{%0,%1,%2,%3}, {%4,%5,%6,%7}, {%8,%9}, {%0,%1,%2,%3};"
                : "+f"(acc[nb][0]), "+f"(acc[nb][1]),
                  "+f"(acc[nb][2]), "+f"(acc[nb][3])
                : "r"(a0), "r"(a1), "r"(a2), "r"(a3),
                  "r"(bfrag[nb][kc][0]), "r"(bfrag[nb][kc][1]));
        }
    }

    const int cc = tig << 1;
    #pragma unroll
    for (int nb = 0; nb < 8; nb++) {
        int c0 = nb * 8 + cc;
        if (v0) g_h[(r0 * D + c0) >> 1] = __floats2half2_rn(acc[nb][0], acc[nb][1]);
        if (v1) g_h[(r1 * D + c0) >> 1] = __floats2half2_rn(acc[nb][2], acc[nb][3]);
    }
}

// ---------------------------------------------------------------------------
// Aggregate (gather form): warp per dst node, unroll x4 for MLP.
// out[d] = relu( dis[d] * ( dis[d]*h[d] + sum_e m_e*h[src_e] ) + b )
__global__ __launch_bounds__(256) void k_aggr(const float* __restrict__ b,
                                              float* __restrict__ out) {
    int gw   = (blockIdx.x * 256 + threadIdx.x) >> 5;
    int lane = threadIdx.x & 31;
    if (gw >= NN) return;

    int off = g_off[gw];
    int end = g_off[gw + 1];
    float dd = g_dis[gw];

    float2 hd = __half22float2(g_h[gw * (D / 2) + lane]);
    float2 acc = make_float2(dd * hd.x, dd * hd.y);

    for (int eb = off; eb < end; eb += 32) {
        int n = min(32, end - eb);
        int2 pk = make_int2(0, 0);
        if (lane < n) pk = g_pack[eb + lane];
        int j = 0;
        for (; j + 4 <= n; j += 4) {
            int   s0 = __shfl_sync(0xffffffffu, pk.x, j);
            int   s1 = __shfl_sync(0xffffffffu, pk.x, j + 1);
            int   s2 = __shfl_sync(0xffffffffu, pk.x, j + 2);
            int   s3 = __shfl_sync(0xffffffffu, pk.x, j + 3);
            float m0 = __int_as_float(__shfl_sync(0xffffffffu, pk.y, j));
            float m1 = __int_as_float(__shfl_sync(0xffffffffu, pk.y, j + 1));
            float m2 = __int_as_float(__shfl_sync(0xffffffffu, pk.y, j + 2));
            float m3 = __int_as_float(__shfl_sync(0xffffffffu, pk.y, j + 3));
            float2 f0 = __half22float2(g_h[s0 * (D / 2) + lane]);
            float2 f1 = __half22float2(g_h[s1 * (D / 2) + lane]);
            float2 f2 = __half22float2(g_h[s2 * (D / 2) + lane]);
            float2 f3 = __half22float2(g_h[s3 * (D / 2) + lane]);
            acc.x = fmaf(m0, f0.x, acc.x); acc.y = fmaf(m0, f0.y, acc.y);
            acc.x = fmaf(m1, f1.x, acc.x); acc.y = fmaf(m1, f1.y, acc.y);
            acc.x = fmaf(m2, f2.x, acc.x); acc.y = fmaf(m2, f2.y, acc.y);
            acc.x = fmaf(m3, f3.x, acc.x); acc.y = fmaf(m3, f3.y, acc.y);
        }
        for (; j < n; j++) {
            int   sj = __shfl_sync(0xffffffffu, pk.x, j);
            float mj = __int_as_float(__shfl_sync(0xffffffffu, pk.y, j));
            float2 f = __half22float2(g_h[sj * (D / 2) + lane]);
            acc.x = fmaf(mj, f.x, acc.x);
            acc.y = fmaf(mj, f.y, acc.y);
        }
    }

    float2 bb = *(const float2*)&b[2 * lane];
    float2 o;
    o.x = fmaxf(fmaf(dd, acc.x, bb.x), 0.f);
    o.y = fmaxf(fmaf(dd, acc.y, bb.y), 0.f);
    *(float2*)&out[gw * D + 2 * lane] = o;
}

// ---------------------------------------------------------------------------
extern "C" void kernel_launch(void* const* d_in, const int* in_sizes, int n_in,
                              void* d_out, int out_size) {
    const float* x  = (const float*)d_in[0];
    const int*   ei = (const int*)d_in[1];     // [2, NE] row-major
    const float* ea = (const float*)d_in[2];
    const float* W  = (const float*)d_in[3];
    const float* b  = (const float*)d_in[4];
    float* out = (float*)d_out;

    const int* src = ei;
    const int* dst = ei + NE;

    k_init<<<(NN + 255) / 256, 256>>>();
    k_deg<<<(NE + 255) / 256, 256>>>(dst, ea);
    k_scan1<<<NB, SCAN_B>>>();                  // + fused rsqrt
    k_scan3<<<NB, SCAN_B>>>();                  // scan2 fused in
    k_fill<<<(NE + 255) / 256, 256>>>(src, dst, ea);
    k_gemm<<<(NN + GROWS - 1) / GROWS, 256>>>(x, W);
    k_aggr<<<(NN * 32 + 255) / 256, 256>>>(b, out);
}